// round 4
// baseline (speedup 1.0000x reference)
#include <cuda_runtime.h>
#include <cuda_fp16.h>
#include <math.h>
#include <stdint.h>

// Problem constants
#define BSZ       256
#define NNK       255
#define DIM       128
#define SIGMA_C   0.07f
#define REG_C     0.1f
#define ETA_C     0.001f
#define NITERS    1000

// ---------------- device globals (scratch; no allocations allowed) ----------
__device__ __align__(16) float g_ftr[2 * BSZ * DIM];   // 512 x 128 normalized features
__device__ __align__(16) float g_K[BSZ * 2 * BSZ];     // 256 x 512 fp32 kernel matrix
__device__ __align__(16) float g_partial[BSZ * 8];     // per-batch stats partials

// ---------------- P1: feature normalization --------------------------------
__global__ void norm_kernel(const float* __restrict__ z) {
    int b = blockIdx.x;
    int d = threadIdx.x;
    float z0 = z[(b * 2 + 0) * DIM + d];
    float z1 = z[(b * 2 + 1) * DIM + d];
    float n = fmaxf(sqrtf(z0 * z0 + z1 * z1), 1e-12f);
    g_ftr[b * DIM + d]         = z0 / n;
    g_ftr[(BSZ + b) * DIM + d] = z1 / n;
}

// ---------------- P2: RBF kernel matrix K (256 x 512) ----------------------
__global__ void rbf_kernel_mat() {
    __shared__ float fi[DIM];
    int i = blockIdx.x;
    if (threadIdx.x < DIM) fi[threadIdx.x] = g_ftr[i * DIM + threadIdx.x];
    __syncthreads();
    for (int j = threadIdx.x; j < 2 * BSZ; j += blockDim.x) {
        const float* fj = &g_ftr[j * DIM];
        float d = 0.0f;
        #pragma unroll 8
        for (int c = 0; c < DIM; ++c) {
            float df = fi[c] - fj[c];
            d = fmaf(df, df, d);
        }
        g_K[i * (2 * BSZ) + j] = expf(-SIGMA_C * d);
    }
}

// ---------------- HMMA helper ------------------------------------------------
__device__ __forceinline__ void mma16816(float* d, const uint32_t* a,
                                         uint32_t b0, uint32_t b1) {
    asm volatile(
        "mma.sync.aligned.m16n8k16.row.col.f32.f16.f16.f32 "
        "{%0,%1,%2,%3}, {%4,%5,%6,%7}, {%8,%9}, {%0,%1,%2,%3};"
        : "+f"(d[0]), "+f"(d[1]), "+f"(d[2]), "+f"(d[3])
        : "r"(a[0]), "r"(a[1]), "r"(a[2]), "r"(a[3]), "r"(b0), "r"(b1));
}

__device__ __forceinline__ uint32_t packh2(float lo, float hi) {
    __half2 h = __floats2half2_rn(lo, hi);
    return *(uint32_t*)&h;
}

__device__ __forceinline__ float blkred(float v, volatile float* scr, int tid) {
    scr[tid] = v;
    __syncthreads();
    #pragma unroll
    for (int s = 128; s > 0; s >>= 1) {
        if (tid < s) scr[tid] = scr[tid] + scr[tid + s];
        __syncthreads();
    }
    float r = scr[0];
    __syncthreads();
    return r;
}

// ---------------- P3: persistent HMMA-PGD kernel ----------------------------
// 128 CTAs x 256 threads (8 warps); CTA c owns batches (2c, 2c+1).
// KK (fp16, zero-diag) lives in REGISTERS as mma A-fragments: 128 regs/thread.
// 2 barriers/iter: bar1 publishes ys; bar2 publishes (Sum c, Sum c^2, Gb).
__global__ void __launch_bounds__(256, 1)
pgd_kernel(const float* __restrict__ alpha_init) {
    __shared__ __half  ys0h[256];
    __shared__ __half  ys1h[256];
    __shared__ float4  red4[8];     // per-warp (Sc0, Sc0^2, Sc1, Sc1^2)
    __shared__ float   GbS[2];
    __shared__ float   scr[256];    // tail reductions only

    const int tid  = threadIdx.x;
    const int wid  = tid >> 5;
    const int lane = tid & 31;
    const int gid  = lane >> 2;    // fragment group id
    const int tig  = lane & 3;     // thread-in-group
    const int b0 = blockIdx.x * 2;
    const int b1 = b0 + 1;
    const int R  = wid * 32;       // this warp's row base

    // ---- prologue: load A fragments (KK fp16, zero diagonal) into registers
    uint32_t afr[2][16][4];
    #pragma unroll
    for (int mt = 0; mt < 2; ++mt) {
        const int r0 = R + mt * 16 + gid;
        const int r1 = r0 + 8;
        #pragma unroll
        for (int kt = 0; kt < 16; ++kt) {
            const int c = kt * 16 + 2 * tig;
            float v00 = (r0 == c)     ? 0.f : g_K[r0 * 512 + c];
            float v01 = (r0 == c + 1) ? 0.f : g_K[r0 * 512 + c + 1];
            float v10 = (r1 == c)     ? 0.f : g_K[r1 * 512 + c];
            float v11 = (r1 == c + 1) ? 0.f : g_K[r1 * 512 + c + 1];
            float w00 = (r0 == c + 8) ? 0.f : g_K[r0 * 512 + c + 8];
            float w01 = (r0 == c + 9) ? 0.f : g_K[r0 * 512 + c + 9];
            float w10 = (r1 == c + 8) ? 0.f : g_K[r1 * 512 + c + 8];
            float w11 = (r1 == c + 9) ? 0.f : g_K[r1 * 512 + c + 9];
            afr[mt][kt][0] = packh2(v00, v01);
            afr[mt][kt][1] = packh2(v10, v11);
            afr[mt][kt][2] = packh2(w00, w01);
            afr[mt][kt][3] = packh2(w10, w11);
        }
    }

    // fp32 rows b0, b1 of KK (rank-one term), per-thread
    const float rK0 = g_K[b0 * 512 + tid];
    const float rK1 = g_K[b1 * 512 + tid];

    // Per-thread state: thread tid owns scatter slot tid for both batches.
    const bool v0 = (tid != b0), v1 = (tid != b1);
    float a0 = 0.f, ap0 = 0.f, a1 = 0.f, ap1 = 0.f;
    if (v0) { int i0 = tid - (tid > b0); a0 = fminf(fmaxf(alpha_init[b0 * NNK + i0], 0.f), 1.f); ap0 = a0; }
    if (v1) { int i1 = tid - (tid > b1); a1 = fminf(fmaxf(alpha_init[b1 * NNK + i1], 0.f), 1.f); ap1 = a1; }

    // B-fragment load base: column gid of B -> gid==0: ys0, gid==1: ys1, else 0
    const uint32_t* yb = (gid == 1) ? (const uint32_t*)ys1h : (const uint32_t*)ys0h;
    const bool bactive = (gid < 2);
    const __half2* y0h2 = (const __half2*)ys0h;
    const __half2* y1h2 = (const __half2*)ys1h;
    const int src = (lane & 7) << 2;     // redistribution source lane
    const int qq  = lane >> 3;           // redistribution register selector

    __syncthreads();

    for (int it = 0; it < NITERS; ++it) {
        float tf = (float)it;
        float beta = tf / (tf + 3.0f);
        float y0 = v0 ? fmaf(beta, a0 - ap0, a0) : 0.f;
        float y1 = v1 ? fmaf(beta, a1 - ap1, a1) : 0.f;
        ys0h[tid] = __float2half(y0);
        ys1h[tid] = __float2half(y1);
        __syncthreads();                                        // bar 1

        // ---- HMMA matvec (4 independent accumulator chains) + S reduce ----
        float d0lo[4] = {0,0,0,0}, d0hi[4] = {0,0,0,0};
        float d1lo[4] = {0,0,0,0}, d1hi[4] = {0,0,0,0};
        #pragma unroll
        for (int kt = 0; kt < 8; ++kt) {
            uint32_t bf0 = 0u, bf1 = 0u, cf0 = 0u, cf1 = 0u;
            if (bactive) {
                bf0 = yb[kt * 8 + tig];
                bf1 = yb[kt * 8 + tig + 4];
                cf0 = yb[(kt + 8) * 8 + tig];
                cf1 = yb[(kt + 8) * 8 + tig + 4];
            }
            mma16816(d0lo, afr[0][kt],     bf0, bf1);
            mma16816(d1lo, afr[1][kt],     bf0, bf1);
            mma16816(d0hi, afr[0][kt + 8], cf0, cf1);
            mma16816(d1hi, afr[1][kt + 8], cf0, cf1);
        }
        // S = sum(ys) computed redundantly from smem (overlaps MMA stalls)
        float2 sp0 = __half22float2(y0h2[lane]);
        float2 sp1 = __half22float2(y1h2[lane]);
        #pragma unroll
        for (int r = 1; r < 4; ++r) {
            float2 t0 = __half22float2(y0h2[lane + 32 * r]);
            float2 t1 = __half22float2(y1h2[lane + 32 * r]);
            sp0.x += t0.x; sp0.y += t0.y;
            sp1.x += t1.x; sp1.y += t1.y;
        }
        float S0 = sp0.x + sp0.y;
        float S1 = sp1.x + sp1.y;
        #pragma unroll
        for (int off = 16; off; off >>= 1) {
            S0 += __shfl_xor_sync(0xffffffffu, S0, off);
            S1 += __shfl_xor_sync(0xffffffffu, S1, off);
        }

        float d0[4], d1[4];
        #pragma unroll
        for (int i = 0; i < 4; ++i) { d0[i] = d0lo[i] + d0hi[i]; d1[i] = d1lo[i] + d1hi[i]; }

        // ---- in-warp redistribution: thread tid gets G[row tid] ----
        float g00 = __shfl_sync(0xffffffffu, d0[0], src);
        float g01 = __shfl_sync(0xffffffffu, d0[2], src);
        float g02 = __shfl_sync(0xffffffffu, d1[0], src);
        float g03 = __shfl_sync(0xffffffffu, d1[2], src);
        float g10 = __shfl_sync(0xffffffffu, d0[1], src);
        float g11 = __shfl_sync(0xffffffffu, d0[3], src);
        float g12 = __shfl_sync(0xffffffffu, d1[1], src);
        float g13 = __shfl_sync(0xffffffffu, d1[3], src);
        float G0 = (qq < 2) ? ((qq == 0) ? g00 : g01) : ((qq == 2) ? g02 : g03);
        float G1 = (qq < 2) ? ((qq == 0) ? g10 : g11) : ((qq == 2) ? g12 : g13);

        // c = S*(1 - rowK) + 1.1*y + G - 2   (grad = c - G[b]; diag via +y)
        float c0 = v0 ? fmaf(1.0f - rK0, S0, fmaf(1.1f, y0, G0 - 2.0f)) : 0.f;
        float c1 = v1 ? fmaf(1.0f - rK1, S1, fmaf(1.1f, y1, G1 - 2.0f)) : 0.f;
        if (tid == b0) GbS[0] = G0;
        if (tid == b1) GbS[1] = G1;

        // reduce (Sum c, Sum c^2) for both batches, 4 pipelined chains
        float p0 = c0, q0 = c0 * c0, p1 = c1, q1 = c1 * c1;
        #pragma unroll
        for (int off = 16; off; off >>= 1) {
            p0 += __shfl_xor_sync(0xffffffffu, p0, off);
            q0 += __shfl_xor_sync(0xffffffffu, q0, off);
            p1 += __shfl_xor_sync(0xffffffffu, p1, off);
            q1 += __shfl_xor_sync(0xffffffffu, q1, off);
        }
        if (lane == 0) red4[wid] = make_float4(p0, q0, p1, q1);
        __syncthreads();                                        // bar 2

        float P0 = 0.f, Q0 = 0.f, P1 = 0.f, Q1 = 0.f;
        #pragma unroll
        for (int w = 0; w < 8; ++w) {
            float4 r = red4[w];
            P0 += r.x; Q0 += r.y; P1 += r.z; Q1 += r.w;
        }
        float Gb0 = GbS[0], Gb1 = GbS[1];
        // N = Sum c^2 - 2 Gb Sum c + 255 Gb^2
        float N0 = fmaf(255.f * Gb0, Gb0, fmaf(-2.f * Gb0, P0, Q0));
        float N1 = fmaf(255.f * Gb1, Gb1, fmaf(-2.f * Gb1, P1, Q1));
        float inv0 = 1.0f / (sqrtf(N0) + 1e-12f);
        float inv1 = 1.0f / (sqrtf(N1) + 1e-12f);

        if (v0) { float an = fminf(fmaxf(fmaf(-ETA_C * inv0, c0 - Gb0, y0), 0.f), 1.f); ap0 = a0; a0 = an; }
        if (v1) { float an = fminf(fmaxf(fmaf(-ETA_C * inv1, c1 - Gb1, y1), 0.f), 1.f); ap1 = a1; a1 = an; }
    }

    // ---- tail: per-batch loss/stat partials ----
    __syncthreads();
    float knt0 = g_K[tid * 512 + 256 + b0];   // Ks[k=tid][b0]
    float knt1 = g_K[tid * 512 + 256 + b1];

    float ax0 = blkred(v0 ? a0 : 0.f, scr, tid);
    float ng0 = blkred(v0 ? a0 * knt0 : 0.f, scr, tid);
    float kt0 = blkred(v0 ? knt0 : 0.f, scr, tid);
    float c10 = blkred((v0 && a0 == 1.0f) ? 1.f : 0.f, scr, tid);
    float cp0 = blkred((v0 && a0 > 0.0f) ? 1.f : 0.f, scr, tid);
    float cz0 = blkred((v0 && a0 == 0.0f) ? 1.f : 0.f, scr, tid);

    float ax1 = blkred(v1 ? a1 : 0.f, scr, tid);
    float ng1 = blkred(v1 ? a1 * knt1 : 0.f, scr, tid);
    float kt1 = blkred(v1 ? knt1 : 0.f, scr, tid);
    float c11 = blkred((v1 && a1 == 1.0f) ? 1.f : 0.f, scr, tid);
    float cp1 = blkred((v1 && a1 > 0.0f) ? 1.f : 0.f, scr, tid);
    float cz1 = blkred((v1 && a1 == 0.0f) ? 1.f : 0.f, scr, tid);

    if (tid == 0) {
        float pos0 = g_K[b0 * 512 + 256 + b0];
        float pos1 = g_K[b1 * 512 + 256 + b1];
        float* P0 = &g_partial[b0 * 8];
        P0[0] = ax0 * pos0; P0[1] = ng0; P0[2] = pos0; P0[3] = kt0;
        P0[4] = c10; P0[5] = cp0; P0[6] = cz0;
        float* P1 = &g_partial[b1 * 8];
        P1[0] = ax1 * pos1; P1[1] = ng1; P1[2] = pos1; P1[3] = kt1;
        P1[4] = c11; P1[5] = cp1; P1[6] = cz1;
    }
}

// ---------------- P4: tiny finisher ----------------------------------------
__global__ void finish_kernel(float* __restrict__ out) {
    __shared__ float red[256];
    int b = threadIdx.x;
    float v0 = g_partial[b * 8 + 0];
    float v1 = g_partial[b * 8 + 1];
    float v2 = g_partial[b * 8 + 2];
    float v3 = g_partial[b * 8 + 3];
    float v4 = g_partial[b * 8 + 4];
    float v5 = g_partial[b * 8 + 5];
    float v6 = g_partial[b * 8 + 6];

    float S0 = blkred(v0, red, b);
    float S1 = blkred(v1, red, b);
    float S2 = blkred(v2, red, b);
    float S3 = blkred(v3, red, b);
    float S4 = blkred(v4, red, b);
    float S5 = blkred(v5, red, b);
    float S6 = blkred(v6, red, b);

    if (b == 0) {
        out[0] = S1 / (float)BSZ - S0 / (float)BSZ;       // neg_loss - pos_loss
        out[1] = S2 / (float)BSZ;                          // pos.mean()
        out[2] = S3 / ((float)BSZ * (float)NNK);           // KnT.mean()
        out[3] = S4 / (S5 + 1e-10f);                       // sparsity
        out[4] = S6 / ((float)BSZ * (float)NNK);           // num_zero
        out[5] = 0.0f;
    }
}

// ---------------- launch ----------------------------------------------------
extern "C" void kernel_launch(void* const* d_in, const int* in_sizes, int n_in,
                              void* d_out, int out_size) {
    const float* z  = (const float*)d_in[0];
    const float* ai = (const float*)d_in[1];
    if (n_in >= 2 && in_sizes[0] == BSZ * NNK && in_sizes[1] == BSZ * 2 * DIM) {
        const float* tmp = z; z = ai; ai = tmp;
    }

    norm_kernel<<<BSZ, DIM>>>(z);
    rbf_kernel_mat<<<BSZ, 256>>>();
    pgd_kernel<<<BSZ / 2, 256>>>(ai);
    finish_kernel<<<1, 256>>>((float*)d_out);
}

// round 5
// speedup vs baseline: 1.2952x; 1.2952x over previous
#include <cuda_runtime.h>
#include <cuda_fp16.h>
#include <math.h>
#include <stdint.h>

// Problem constants
#define BSZ       256
#define NNK       255
#define DIM       128
#define SIGMA_C   0.07f
#define REG_C     0.1f
#define ETA_C     0.001f
#define NITERS    1000

// ---------------- device globals (scratch; no allocations allowed) ----------
__device__ __align__(16) float g_ftr[2 * BSZ * DIM];   // 512 x 128 normalized features
__device__ __align__(16) float g_K[BSZ * 2 * BSZ];     // 256 x 512 fp32 kernel matrix
__device__ __align__(16) float g_partial[BSZ * 8];     // per-batch stats partials

// ---------------- P1: feature normalization --------------------------------
__global__ void norm_kernel(const float* __restrict__ z) {
    int b = blockIdx.x;
    int d = threadIdx.x;
    float z0 = z[(b * 2 + 0) * DIM + d];
    float z1 = z[(b * 2 + 1) * DIM + d];
    float n = fmaxf(sqrtf(z0 * z0 + z1 * z1), 1e-12f);
    g_ftr[b * DIM + d]         = z0 / n;
    g_ftr[(BSZ + b) * DIM + d] = z1 / n;
}

// ---------------- P2: RBF kernel matrix K (256 x 512) ----------------------
__global__ void rbf_kernel_mat() {
    __shared__ float fi[DIM];
    int i = blockIdx.x;
    if (threadIdx.x < DIM) fi[threadIdx.x] = g_ftr[i * DIM + threadIdx.x];
    __syncthreads();
    for (int j = threadIdx.x; j < 2 * BSZ; j += blockDim.x) {
        const float* fj = &g_ftr[j * DIM];
        float d = 0.0f;
        #pragma unroll 8
        for (int c = 0; c < DIM; ++c) {
            float df = fi[c] - fj[c];
            d = fmaf(df, df, d);
        }
        g_K[i * (2 * BSZ) + j] = expf(-SIGMA_C * d);
    }
}

// ---------------- MMA / LDSM helpers ----------------------------------------
__device__ __forceinline__ void mma16816(float* d, const uint32_t* a,
                                         uint32_t b0, uint32_t b1) {
    asm volatile(
        "mma.sync.aligned.m16n8k16.row.col.f32.f16.f16.f32 "
        "{%0,%1,%2,%3}, {%4,%5,%6,%7}, {%8,%9}, {%0,%1,%2,%3};"
        : "+f"(d[0]), "+f"(d[1]), "+f"(d[2]), "+f"(d[3])
        : "r"(a[0]), "r"(a[1]), "r"(a[2]), "r"(a[3]), "r"(b0), "r"(b1));
}

__device__ __forceinline__ void ldsm4t(uint32_t& r0, uint32_t& r1,
                                       uint32_t& r2, uint32_t& r3, uint32_t addr) {
    asm volatile("ldmatrix.sync.aligned.m8n8.x4.trans.shared.b16 {%0,%1,%2,%3}, [%4];"
                 : "=r"(r0), "=r"(r1), "=r"(r2), "=r"(r3) : "r"(addr));
}

__device__ __forceinline__ uint32_t packh2(float lo, float hi) {
    __half2 h = __floats2half2_rn(lo, hi);
    return *(uint32_t*)&h;
}

__device__ __forceinline__ float blkred(float v, volatile float* scr, int tid) {
    scr[tid] = v;
    __syncthreads();
    #pragma unroll
    for (int s = 128; s > 0; s >>= 1) {
        if (tid < s) scr[tid] = scr[tid] + scr[tid + s];
        __syncthreads();
    }
    float r = scr[0];
    __syncthreads();
    return r;
}

// ---------------- P3: persistent HMMA-PGD kernel ----------------------------
// 128 CTAs x 512 threads (16 warps, 4/SMSP); CTA c owns batches (2c, 2c+1).
// Warp w owns m-tile rows [16w, 16w+16). Thread t owns (batch t>>8, slot t&255).
// KK fp16 zero-diag A-fragments in registers (64 regs/thread).
// B via ldmatrix.x4.trans from Bmat[256][8] (cols 0,1 live; 2-7 zero).
// S tracked via running scalars: S = Sa + beta*(Sa - Sap).
__global__ void __launch_bounds__(512, 1)
pgd_kernel(const float* __restrict__ alpha_init) {
    __shared__ __align__(16) __half Bmat[256 * 8];   // [slot][col] 4KB
    __shared__ float Gp[2 * 256];                    // [batch][row]
    __shared__ __align__(32) float SaPart[16];
    __shared__ __align__(32) float NPart[16];
    __shared__ float Wst[16][6];                     // tail stats partials

    const int tid  = threadIdx.x;
    const int wid  = tid >> 5;
    const int lane = tid & 31;
    const int gid  = lane >> 2;
    const int tig  = lane & 3;
    const int h    = tid >> 8;        // batch half (0/1)
    const int s    = tid & 255;       // slot
    const int b0   = blockIdx.x * 2;
    const int bh   = b0 + h;
    const int R    = wid * 16;        // this warp's m-tile row base

    // ---- prologue: A fragments (KK fp16, zero diagonal), 1 m-tile per warp
    uint32_t afr[16][4];
    {
        const int r0 = R + gid;
        const int r1 = r0 + 8;
        #pragma unroll
        for (int kt = 0; kt < 16; ++kt) {
            const int c = kt * 16 + 2 * tig;
            float v00 = (r0 == c)     ? 0.f : g_K[r0 * 512 + c];
            float v01 = (r0 == c + 1) ? 0.f : g_K[r0 * 512 + c + 1];
            float v10 = (r1 == c)     ? 0.f : g_K[r1 * 512 + c];
            float v11 = (r1 == c + 1) ? 0.f : g_K[r1 * 512 + c + 1];
            float w00 = (r0 == c + 8) ? 0.f : g_K[r0 * 512 + c + 8];
            float w01 = (r0 == c + 9) ? 0.f : g_K[r0 * 512 + c + 9];
            float w10 = (r1 == c + 8) ? 0.f : g_K[r1 * 512 + c + 8];
            float w11 = (r1 == c + 9) ? 0.f : g_K[r1 * 512 + c + 9];
            afr[kt][0] = packh2(v00, v01);
            afr[kt][1] = packh2(v10, v11);
            afr[kt][2] = packh2(w00, w01);
            afr[kt][3] = packh2(w10, w11);
        }
    }

    // zero Bmat (cols 2..7 stay zero forever)
    ((uint32_t*)Bmat)[tid]       = 0u;
    ((uint32_t*)Bmat)[tid + 512] = 0u;

    // per-thread constants / state
    const float rK  = g_K[bh * 512 + s];
    const bool  vld = (s != bh);
    float a = 0.f, ap = 0.f;
    if (vld) {
        int i = s - (s > bh);
        a = fminf(fmaxf(alpha_init[bh * NNK + i], 0.f), 1.f);
        ap = a;
    }

    // prologue Sigma(a) warp partials (consumed after first bar1)
    {
        float t = a;
        #pragma unroll
        for (int off = 16; off; off >>= 1) t += __shfl_xor_sync(0xffffffffu, t, off);
        if (lane == 0) SaPart[wid] = t;
    }
    float Sa = 0.f;   // junk until first sum; beta(0)=0 makes Sap irrelevant at it=0

    const uint32_t baddr =
        (uint32_t)__cvta_generic_to_shared(Bmat) + (uint32_t)lane * 16u;

    __syncthreads();

    for (int it = 0; it < NITERS; ++it) {
        float tf   = (float)it;
        float beta = __fdividef(tf, tf + 3.0f);
        float y    = vld ? fmaf(beta, a - ap, a) : 0.f;
        Bmat[s * 8 + h] = __float2half(y);
        __syncthreads();                                      // bar 1

        // running-scalar S (partials published before bar1)
        float Sap = Sa;
        {
            float4 p0 = *(const float4*)&SaPart[h * 8];
            float4 p1 = *(const float4*)&SaPart[h * 8 + 4];
            Sa = ((p0.x + p0.y) + (p0.z + p0.w)) + ((p1.x + p1.y) + (p1.z + p1.w));
        }
        float S = fmaf(beta, Sa - Sap, Sa);

        // ---- HMMA matvec: 8x (ldmatrix.x4.trans -> 2 MMAs), 2 acc chains ----
        float dA[4] = {0, 0, 0, 0}, dB[4] = {0, 0, 0, 0};
        #pragma unroll
        for (int c2 = 0; c2 < 8; ++c2) {
            uint32_t r0, r1, r2, r3;
            ldsm4t(r0, r1, r2, r3, baddr + (uint32_t)c2 * 512u);
            mma16816(dA, afr[2 * c2],     r0, r1);
            mma16816(dB, afr[2 * c2 + 1], r2, r3);
        }
        if (tig == 0) {
            int r = R + gid;
            Gp[r]           = dA[0] + dB[0];   // batch0, row r
            Gp[256 + r]     = dA[1] + dB[1];   // batch1, row r
            Gp[r + 8]       = dA[2] + dB[2];
            Gp[256 + r + 8] = dA[3] + dB[3];
        }
        __syncthreads();                                      // bar 2

        float G  = Gp[h * 256 + s];
        float Gb = Gp[h * 256 + bh];
        // c = S*(1 - rowK) + 1.1*y + G - 2 ; grad = c - Gb (diag exact via +y)
        float gv = vld ? (fmaf(1.0f - rK, S, fmaf(1.1f, y, G - 2.0f)) - Gb) : 0.f;

        float nn = gv * gv;
        #pragma unroll
        for (int off = 16; off; off >>= 1) nn += __shfl_xor_sync(0xffffffffu, nn, off);
        if (lane == 0) NPart[wid] = nn;
        __syncthreads();                                      // bar 3

        float N;
        {
            float4 p0 = *(const float4*)&NPart[h * 8];
            float4 p1 = *(const float4*)&NPart[h * 8 + 4];
            N = ((p0.x + p0.y) + (p0.z + p0.w)) + ((p1.x + p1.y) + (p1.z + p1.w));
        }
        float inv = rsqrtf(fmaxf(N, 1e-24f));

        if (vld) {
            float an = fminf(fmaxf(fmaf(-ETA_C * inv, gv, y), 0.f), 1.f);
            ap = a; a = an;
        }

        // publish Sigma(a_new) partials for next iteration (visible after bar1)
        float t = a;
        #pragma unroll
        for (int off = 16; off; off >>= 1) t += __shfl_xor_sync(0xffffffffu, t, off);
        if (lane == 0) SaPart[wid] = t;
    }

    // ---- tail: per-batch loss/stat partials ----
    {
        float knt = g_K[s * 512 + 256 + bh];   // Ks[k=s][bh]
        float v[6];
        v[0] = vld ? a : 0.f;                  // Sigma alpha
        v[1] = vld ? a * knt : 0.f;            // Sigma alpha*KnT
        v[2] = vld ? knt : 0.f;                // Sigma KnT
        v[3] = (vld && a == 1.0f) ? 1.f : 0.f;
        v[4] = (vld && a > 0.0f) ? 1.f : 0.f;
        v[5] = (vld && a == 0.0f) ? 1.f : 0.f;
        #pragma unroll
        for (int j = 0; j < 6; ++j) {
            float t = v[j];
            #pragma unroll
            for (int off = 16; off; off >>= 1) t += __shfl_xor_sync(0xffffffffu, t, off);
            if (lane == 0) Wst[wid][j] = t;
        }
        __syncthreads();
        if (lane == 0 && (wid == 0 || wid == 8)) {
            int wb = (wid == 0) ? 0 : 8;
            int bb = b0 + (wid >> 3);
            float sum[6] = {0, 0, 0, 0, 0, 0};
            #pragma unroll
            for (int w = 0; w < 8; ++w)
                #pragma unroll
                for (int j = 0; j < 6; ++j) sum[j] += Wst[wb + w][j];
            float pos = g_K[bb * 512 + 256 + bb];
            float* P = &g_partial[bb * 8];
            P[0] = sum[0] * pos;   // alpha_x * pos
            P[1] = sum[1];         // Sigma alpha*KnT
            P[2] = pos;
            P[3] = sum[2];
            P[4] = sum[3];
            P[5] = sum[4];
            P[6] = sum[5];
        }
    }
}

// ---------------- P4: tiny finisher ----------------------------------------
__global__ void finish_kernel(float* __restrict__ out) {
    __shared__ float red[256];
    int b = threadIdx.x;
    float v0 = g_partial[b * 8 + 0];
    float v1 = g_partial[b * 8 + 1];
    float v2 = g_partial[b * 8 + 2];
    float v3 = g_partial[b * 8 + 3];
    float v4 = g_partial[b * 8 + 4];
    float v5 = g_partial[b * 8 + 5];
    float v6 = g_partial[b * 8 + 6];

    float S0 = blkred(v0, red, b);
    float S1 = blkred(v1, red, b);
    float S2 = blkred(v2, red, b);
    float S3 = blkred(v3, red, b);
    float S4 = blkred(v4, red, b);
    float S5 = blkred(v5, red, b);
    float S6 = blkred(v6, red, b);

    if (b == 0) {
        out[0] = S1 / (float)BSZ - S0 / (float)BSZ;       // neg_loss - pos_loss
        out[1] = S2 / (float)BSZ;                          // pos.mean()
        out[2] = S3 / ((float)BSZ * (float)NNK);           // KnT.mean()
        out[3] = S4 / (S5 + 1e-10f);                       // sparsity
        out[4] = S6 / ((float)BSZ * (float)NNK);           // num_zero
        out[5] = 0.0f;
    }
}

// ---------------- launch ----------------------------------------------------
extern "C" void kernel_launch(void* const* d_in, const int* in_sizes, int n_in,
                              void* d_out, int out_size) {
    const float* z  = (const float*)d_in[0];
    const float* ai = (const float*)d_in[1];
    if (n_in >= 2 && in_sizes[0] == BSZ * NNK && in_sizes[1] == BSZ * 2 * DIM) {
        const float* tmp = z; z = ai; ai = tmp;
    }

    norm_kernel<<<BSZ, DIM>>>(z);
    rbf_kernel_mat<<<BSZ, 256>>>();
    pgd_kernel<<<BSZ / 2, 512>>>(ai);
    finish_kernel<<<1, 256>>>((float*)d_out);
}